// round 4
// baseline (speedup 1.0000x reference)
#include <cuda_runtime.h>
#include <cuda_bf16.h>
#include <cstdint>

#define N_NODES 50000
#define N_RELS  8
#define IN_DIM  128
#define OUT_DIM 128
#define N_EDGES 800000
#define MT      64
#define M_TILES ((N_NODES + MT - 1) / MT)   // 782

// Scratch (__device__ globals: allocation-free rule)
__device__ __align__(16) float g_h[(size_t)N_RELS * N_NODES * OUT_DIM]; // 204.8 MB
__device__ float g_counts[N_RELS * N_NODES];                            // 1.6 MB
__device__ __align__(16) __nv_bfloat16 g_wt_hi[N_RELS * 128 * 128];     // W^T hi [r][o][k]
__device__ __align__(16) __nv_bfloat16 g_wt_lo[N_RELS * 128 * 128];     // W^T lo [r][o][k]
__device__ int g_rel_hist[N_RELS];
__device__ int g_rel_cursor[N_RELS];
__device__ int g_edge_order[N_EDGES];                                   // 3.2 MB

// ---------------------------------------------------------------------------
// warp-mma helpers (baseline PTX ISA — safe for plain sm_103 ptx target)
// ---------------------------------------------------------------------------
__device__ __forceinline__ uint32_t smem_u32(const void* p) {
    uint32_t a;
    asm("{ .reg .u64 t; cvta.to.shared.u64 t, %1; cvt.u32.u64 %0, t; }"
        : "=r"(a) : "l"(p));
    return a;
}

__device__ __forceinline__ void ldsm4(uint32_t* r, uint32_t addr) {
    asm volatile("ldmatrix.sync.aligned.m8n8.x4.shared.b16 {%0,%1,%2,%3}, [%4];"
                 : "=r"(r[0]), "=r"(r[1]), "=r"(r[2]), "=r"(r[3]) : "r"(addr));
}

__device__ __forceinline__ void mma_bf16(float* d, const uint32_t* a, const uint32_t* b) {
    asm volatile(
        "mma.sync.aligned.m16n8k16.row.col.f32.bf16.bf16.f32 "
        "{%0,%1,%2,%3}, {%4,%5,%6,%7}, {%8,%9}, {%0,%1,%2,%3};"
        : "+f"(d[0]), "+f"(d[1]), "+f"(d[2]), "+f"(d[3])
        : "r"(a[0]), "r"(a[1]), "r"(a[2]), "r"(a[3]), "r"(b[0]), "r"(b[1]));
}

// tile row = 256B (128 bf16) = 16 chunks of 16B; chunk' = chunk ^ (row&7)
__device__ __forceinline__ uint32_t sw_off(int row, int chunk) {
    return (uint32_t)(row * 256 + ((chunk ^ (row & 7)) << 4));
}

// SMEM layout: Ahi 16KB | Alo 16KB | Bhi 32KB | Blo 32KB = 96KB
#define SM_AH 0
#define SM_AL 16384
#define SM_BH 32768
#define SM_BL 65536
#define SMEM_TOTAL 98304

// ---------------------------------------------------------------------------
// Kernel 1: out = bias, counts = 0, hist/cursor = 0
// ---------------------------------------------------------------------------
__global__ void init_kernel(float* __restrict__ out, const float* __restrict__ bias) {
    int idx = blockIdx.x * blockDim.x + threadIdx.x;
    int stride = gridDim.x * blockDim.x;
    const int total = N_NODES * OUT_DIM;
    for (int i = idx; i < total; i += stride)
        out[i] = bias[i & (OUT_DIM - 1)];
    for (int i = idx; i < N_RELS * N_NODES; i += stride)
        g_counts[i] = 0.0f;
    if (idx < N_RELS) {
        g_rel_hist[idx] = 0;
        g_rel_cursor[idx] = 0;
    }
}

// ---------------------------------------------------------------------------
// Kernel 2: counts[rel*N + tgt] += 1, plus per-rel histogram
// ---------------------------------------------------------------------------
__global__ void count_kernel(const int* __restrict__ triples) {
    __shared__ int sh[N_RELS];
    if (threadIdx.x < N_RELS) sh[threadIdx.x] = 0;
    __syncthreads();
    int e = blockIdx.x * blockDim.x + threadIdx.x;
    if (e < N_EDGES) {
        int rel = triples[e * 3 + 1];
        int tgt = triples[e * 3 + 2];
        atomicAdd(&g_counts[rel * N_NODES + tgt], 1.0f);
        atomicAdd(&sh[rel], 1);
    }
    __syncthreads();
    if (threadIdx.x < N_RELS)
        atomicAdd(&g_rel_hist[threadIdx.x], sh[threadIdx.x]);
}

// ---------------------------------------------------------------------------
// Kernel 2c: exclusive prefix of rel histogram -> cursors
// ---------------------------------------------------------------------------
__global__ void offsets_kernel() {
    if (threadIdx.x == 0 && blockIdx.x == 0) {
        int s = 0;
        for (int r = 0; r < N_RELS; r++) {
            g_rel_cursor[r] = s;
            s += g_rel_hist[r];
        }
    }
}

// ---------------------------------------------------------------------------
// Kernel 2d: bucket edge ids by relation (warp-aggregated cursor atomics)
// ---------------------------------------------------------------------------
__global__ void bucket_kernel(const int* __restrict__ triples) {
    int e = blockIdx.x * blockDim.x + threadIdx.x;
    if (e >= N_EDGES) return;
    int rel = triples[e * 3 + 1];
    unsigned mask = __match_any_sync(__activemask(), rel);
    int lane = threadIdx.x & 31;
    int leader = __ffs(mask) - 1;
    int rank = __popc(mask & ((1u << lane) - 1));
    int base = 0;
    if (lane == leader)
        base = atomicAdd(&g_rel_cursor[rel], __popc(mask));
    base = __shfl_sync(mask, base, leader);
    g_edge_order[base + rank] = e;
}

// ---------------------------------------------------------------------------
// Kernel 2b: W [r][k][o] fp32 -> Wt hi/lo [r][o][k] bf16 (transpose + split)
// ---------------------------------------------------------------------------
__global__ void split_w_kernel(const float* __restrict__ W) {
    int idx = blockIdx.x * blockDim.x + threadIdx.x;
    if (idx >= N_RELS * 128 * 128) return;
    int r = idx >> 14;
    int k = (idx >> 7) & 127;
    int o = idx & 127;
    float x = W[idx];
    __nv_bfloat16 hi = __float2bfloat16(x);
    __nv_bfloat16 lo = __float2bfloat16(x - __bfloat162float(hi));
    int dst = (r << 14) + (o << 7) + k;
    g_wt_hi[dst] = hi;
    g_wt_lo[dst] = lo;
}

// ---------------------------------------------------------------------------
// Kernel 3: split-bf16 GEMM. One CTA = 64-row m-tile, loops over ALL 8 rels.
//   A converted fp32->bf16 hi/lo ONCE; B_r streamed from L2-resident g_wt.
//   8 warps: warp = 32 rows x 32 cols per rel. 2 CTAs/SM.
// ---------------------------------------------------------------------------
__global__ void __launch_bounds__(256, 2)
gemm_mma_kernel(const float* __restrict__ A) {
    extern __shared__ char smem[];
    const int m0 = blockIdx.x * MT;
    const int tid = threadIdx.x;
    const int wid = tid >> 5;
    const int lid = tid & 31;
    const uint32_t sb = smem_u32(smem);

    // ---- fill A hi/lo (64 rows x 128 bf16 each) ----
#pragma unroll
    for (int i = 0; i < 4; i++) {
        int cid = tid + i * 256;          // 1024 chunks
        int row = cid >> 4;
        int chunk = cid & 15;
        uint32_t so = sw_off(row, chunk);
        int grow = m0 + row;
        if (grow >= N_NODES) grow = 0;    // junk rows; epilogue guards
        const float* p = A + ((size_t)grow << 7) + (chunk << 3);
        float4 x0 = *(const float4*)p;
        float4 x1 = *(const float4*)(p + 4);
        float f[8] = {x0.x, x0.y, x0.z, x0.w, x1.x, x1.y, x1.z, x1.w};
        uint32_t ph[4], pl[4];
#pragma unroll
        for (int j = 0; j < 4; j++) {
            __nv_bfloat162 th, tl;
            float a = f[2 * j], b = f[2 * j + 1];
            th.x = __float2bfloat16(a);
            th.y = __float2bfloat16(b);
            tl.x = __float2bfloat16(a - __bfloat162float(th.x));
            tl.y = __float2bfloat16(b - __bfloat162float(th.y));
            ph[j] = *reinterpret_cast<uint32_t*>(&th);
            pl[j] = *reinterpret_cast<uint32_t*>(&tl);
        }
        *(uint4*)(smem + SM_AH + so) = make_uint4(ph[0], ph[1], ph[2], ph[3]);
        *(uint4*)(smem + SM_AL + so) = make_uint4(pl[0], pl[1], pl[2], pl[3]);
    }

    // ---- per-lane ldmatrix addresses ----
    const int wm = wid & 1;          // 2 m-tiles of 32 rows
    const int wn = wid >> 1;         // 4 n-tiles of 32 cols
    const int a_row = wm * 32 + (lid & 15);
    const int a_kc  = lid >> 4;
    const int a_and = a_row & 7;
    const uint32_t a_base = sb + (uint32_t)(a_row * 256);
    const int b_row = wn * 32 + ((lid >> 4) << 3) + (lid & 7);
    const int b_kc  = (lid >> 3) & 1;
    const int b_and = b_row & 7;     // invariant under +16
    const uint32_t b_base = sb + (uint32_t)(b_row * 256);

    const int col0 = wn * 32 + (lid & 3) * 2;
    const int row_lo = m0 + wm * 32 + (lid >> 2);

#pragma unroll 1
    for (int r = 0; r < N_RELS; r++) {
        // ---- fill B_r (128 o-rows x 128 k) from L2-resident g_wt ----
        const __nv_bfloat16* Bh = g_wt_hi + (r << 14);
        const __nv_bfloat16* Bl = g_wt_lo + (r << 14);
#pragma unroll
        for (int i = 0; i < 8; i++) {
            int cid = tid + i * 256;      // 2048 chunks
            int row = cid >> 4;
            int chunk = cid & 15;
            uint32_t so = sw_off(row, chunk);
            *(uint4*)(smem + SM_BH + so) = *(const uint4*)(Bh + (row << 7) + (chunk << 3));
            *(uint4*)(smem + SM_BL + so) = *(const uint4*)(Bl + (row << 7) + (chunk << 3));
        }
        __syncthreads();

        float acc[2][4][4];
#pragma unroll
        for (int mt = 0; mt < 2; mt++)
#pragma unroll
            for (int nn = 0; nn < 4; nn++)
#pragma unroll
                for (int c = 0; c < 4; c++) acc[mt][nn][c] = 0.0f;

#pragma unroll
        for (int s = 0; s < 8; s++) {
            uint32_t Ah[2][4], Al[2][4], Bh4[2][4], Bl4[2][4];
            const uint32_t ac = (uint32_t)(((s * 2 + a_kc) ^ a_and) << 4);
            const uint32_t bc = (uint32_t)(((s * 2 + b_kc) ^ b_and) << 4);
#pragma unroll
            for (int t = 0; t < 2; t++) {
                ldsm4(Ah[t], a_base + SM_AH + t * 4096 + ac);
                ldsm4(Al[t], a_base + SM_AL + t * 4096 + ac);
                ldsm4(Bh4[t], b_base + SM_BH + t * 4096 + bc);
                ldsm4(Bl4[t], b_base + SM_BL + t * 4096 + bc);
            }
#pragma unroll
            for (int g = 0; g < 2; g++) {
#pragma unroll
                for (int half = 0; half < 2; half++) {
                    const int nn = g * 2 + half;
                    const uint32_t* bh = &Bh4[g][half * 2];
                    const uint32_t* bl = &Bl4[g][half * 2];
#pragma unroll
                    for (int mt = 0; mt < 2; mt++) {
                        mma_bf16(acc[mt][nn], Ah[mt], bh);
                        mma_bf16(acc[mt][nn], Ah[mt], bl);
                        mma_bf16(acc[mt][nn], Al[mt], bh);
                    }
                }
            }
        }
        __syncthreads();   // B consumed; next rel may overwrite

        // ---- epilogue: write fp32 h[r] tile ----
        float* H = g_h + ((size_t)r * N_NODES << 7);
#pragma unroll
        for (int mt = 0; mt < 2; mt++) {
            int row = row_lo + mt * 16;
            if (row < N_NODES) {
                float* Hp = H + ((size_t)row << 7) + col0;
#pragma unroll
                for (int nn = 0; nn < 4; nn++)
                    *(float2*)(Hp + nn * 8) = make_float2(acc[mt][nn][0], acc[mt][nn][1]);
            }
            if (row + 8 < N_NODES) {
                float* Hp = H + ((size_t)(row + 8) << 7) + col0;
#pragma unroll
                for (int nn = 0; nn < 4; nn++)
                    *(float2*)(Hp + nn * 8) = make_float2(acc[mt][nn][2], acc[mt][nn][3]);
            }
        }
    }
}

// ---------------------------------------------------------------------------
// Kernel 4: rel-grouped edges; 8 lanes/edge, 4 float4 gathers/lane
// ---------------------------------------------------------------------------
__global__ void edge_kernel(const int* __restrict__ triples, float* __restrict__ out) {
    int t = blockIdx.x * blockDim.x + threadIdx.x;
    int ei = t >> 3;
    int p = t & 7;
    if (ei >= N_EDGES) return;
    int e = g_edge_order[ei];

    int src = triples[e * 3 + 0];
    int rel = triples[e * 3 + 1];
    int tgt = triples[e * 3 + 2];

    float val = 1.0f / g_counts[rel * N_NODES + tgt];

    const float4* h4 = (const float4*)(g_h + (((size_t)rel * N_NODES + src) << 7)) + p * 4;
    float4 v0 = h4[0];
    float4 v1 = h4[1];
    float4 v2 = h4[2];
    float4 v3 = h4[3];
    v0.x *= val; v0.y *= val; v0.z *= val; v0.w *= val;
    v1.x *= val; v1.y *= val; v1.z *= val; v1.w *= val;
    v2.x *= val; v2.y *= val; v2.z *= val; v2.w *= val;
    v3.x *= val; v3.y *= val; v3.z *= val; v3.w *= val;

    float4* o = (float4*)(out + ((size_t)tgt << 7)) + p * 4;
    asm volatile("red.global.add.v4.f32 [%0], {%1, %2, %3, %4};"
                 :: "l"(o + 0), "f"(v0.x), "f"(v0.y), "f"(v0.z), "f"(v0.w) : "memory");
    asm volatile("red.global.add.v4.f32 [%0], {%1, %2, %3, %4};"
                 :: "l"(o + 1), "f"(v1.x), "f"(v1.y), "f"(v1.z), "f"(v1.w) : "memory");
    asm volatile("red.global.add.v4.f32 [%0], {%1, %2, %3, %4};"
                 :: "l"(o + 2), "f"(v2.x), "f"(v2.y), "f"(v2.z), "f"(v2.w) : "memory");
    asm volatile("red.global.add.v4.f32 [%0], {%1, %2, %3, %4};"
                 :: "l"(o + 3), "f"(v3.x), "f"(v3.y), "f"(v3.z), "f"(v3.w) : "memory");
}

// ---------------------------------------------------------------------------
extern "C" void kernel_launch(void* const* d_in, const int* in_sizes, int n_in,
                              void* d_out, int out_size) {
    const int*   triples  = (const int*)d_in[0];    // [E, 3] (src, rel, tgt)
    const float* features = (const float*)d_in[1];  // [N, 128]
    const float* weights  = (const float*)d_in[2];  // [8, 128, 128]
    const float* bias     = (const float*)d_in[3];  // [128]
    float* out = (float*)d_out;                     // [N, 128]
    (void)in_sizes; (void)n_in; (void)out_size;

    cudaFuncSetAttribute(gemm_mma_kernel,
                         cudaFuncAttributeMaxDynamicSharedMemorySize, SMEM_TOTAL);

    init_kernel<<<1024, 256>>>(out, bias);
    count_kernel<<<(N_EDGES + 255) / 256, 256>>>(triples);
    offsets_kernel<<<1, 32>>>();
    bucket_kernel<<<(N_EDGES + 255) / 256, 256>>>(triples);
    split_w_kernel<<<(N_RELS * 128 * 128 + 255) / 256, 256>>>(weights);

    gemm_mma_kernel<<<M_TILES, 256, SMEM_TOTAL>>>(features);

    edge_kernel<<<(N_EDGES * 8 + 255) / 256, 256>>>(triples, out);
}